// round 1
// baseline (speedup 1.0000x reference)
#include <cuda_runtime.h>
#include <cstdint>

#define B_  50
#define T_  2048
#define D_  65
#define G4  260     // 4*UNITS
#define KP  68      // K padded to multiple of 4
#define NL  3

// Scratch for top-layer hidden states (written by lstm kernel, read by dense kernel)
__device__ float g_hs[(size_t)B_ * T_ * D_];

// ---------------------------------------------------------------------------
// math helpers
// ---------------------------------------------------------------------------
__device__ __forceinline__ float sigmoid_f(float x) {
    // stable: for very negative x, __expf(-x) -> inf, 1/inf -> 0 (IEEE div)
    return 1.0f / (1.0f + __expf(-x));
}
__device__ __forceinline__ float tanh_f(float x) {
    // stable at both ends: e->inf => 1, e->0 => -1
    float e = __expf(2.0f * x);
    return 1.0f - 2.0f / (e + 1.0f);
}

// packed f32x2 FMA (Blackwell): acc.{lo,hi} += a.{lo,hi} * b.{lo,hi}
__device__ __forceinline__ void ffma2(uint64_t& acc, uint64_t a, uint64_t b) {
    asm("fma.rn.f32x2 %0, %1, %2, %0;" : "+l"(acc) : "l"(a), "l"(b));
}
__device__ __forceinline__ uint64_t fadd2(uint64_t a, uint64_t b) {
    uint64_t r;
    asm("add.rn.f32x2 %0, %1, %2;" : "=l"(r) : "l"(a), "l"(b));
    return r;
}
__device__ __forceinline__ float hsum2(uint64_t v) {
    float lo, hi;
    asm("mov.b64 {%0, %1}, %2;" : "=f"(lo), "=f"(hi) : "l"(v));
    return lo + hi;
}
__device__ __forceinline__ uint64_t pack2(float lo, float hi) {
    uint64_t r;
    asm("mov.b64 %0, {%1, %2};" : "=l"(r) : "f"(lo), "f"(hi));
    return r;
}

// ---------------------------------------------------------------------------
// Persistent LSTM kernel: one CTA per batch element, thread j owns z-column j.
// Weights (columns of W and U) live in registers for the whole sequence.
// ---------------------------------------------------------------------------
__global__ void __launch_bounds__(G4, 1) lstm_kernel(
    const float* __restrict__ x,   // [B, T, D]
    const float* __restrict__ W,   // [D, 4D]
    const float* __restrict__ U,   // [D, 4D]
    const float* __restrict__ b)   // [4D]
{
    __shared__ __align__(16) float inp_s[KP];
    __shared__ __align__(16) float h_s[NL][KP];
    __shared__ float z_s[G4];

    const int j  = threadIdx.x;     // 0..259
    const int bb = blockIdx.x;      // batch element

    // ---- load weight columns into packed registers (once per sequence) ----
    uint64_t Wr[KP / 2], Ur[KP / 2];
#pragma unroll
    for (int k = 0; k < KP / 2; k++) {
        float w0 = (2 * k     < D_) ? W[(2 * k    ) * G4 + j] : 0.0f;
        float w1 = (2 * k + 1 < D_) ? W[(2 * k + 1) * G4 + j] : 0.0f;
        Wr[k] = pack2(w0, w1);
        float u0 = (2 * k     < D_) ? U[(2 * k    ) * G4 + j] : 0.0f;
        float u1 = (2 * k + 1 < D_) ? U[(2 * k + 1) * G4 + j] : 0.0f;
        Ur[k] = pack2(u0, u1);
    }
    const float bj   = b[j];
    const int   gsel = j / D_;      // 0=i, 1=f, 2=g, 3=o

    // ---- zero state ----
    if (j < KP) {
        inp_s[j] = 0.0f;
#pragma unroll
        for (int l = 0; l < NL; l++) h_s[l][j] = 0.0f;
    }
    float c0 = 0.0f, c1 = 0.0f, c2 = 0.0f;

    const float* xb = x    + (size_t)bb * T_ * D_;
    float*       hb = g_hs + (size_t)bb * T_ * D_;

    float xr = (j < D_) ? xb[j] : 0.0f;   // prefetch t=0
    __syncthreads();

    for (int t = 0; t < T_; t++) {
        if (j < D_) inp_s[j] = xr;
        __syncthreads();
        // prefetch next timestep's input (latency hidden by layer compute)
        float xn = 0.0f;
        if (j < D_ && t + 1 < T_) xn = xb[(t + 1) * D_ + j];

#pragma unroll
        for (int l = 0; l < NL; l++) {
            const float* in_p = (l == 0) ? inp_s : h_s[l - 1];
            const ulonglong2* in2 = reinterpret_cast<const ulonglong2*>(in_p);
            const ulonglong2* h2  = reinterpret_cast<const ulonglong2*>(h_s[l]);

            uint64_t aW = 0, aU = 0;   // packed {0.f, 0.f}
#pragma unroll
            for (int k = 0; k < KP / 4; k++) {
                ulonglong2 iv = in2[k];   // 4 input floats (broadcast LDS.128)
                ulonglong2 hv = h2[k];    // 4 hidden floats
                ffma2(aW, iv.x, Wr[2 * k]);
                ffma2(aW, iv.y, Wr[2 * k + 1]);
                ffma2(aU, hv.x, Ur[2 * k]);
                ffma2(aU, hv.y, Ur[2 * k + 1]);
            }
            float z = hsum2(fadd2(aW, aU)) + bj;
            float a = (gsel == 2) ? tanh_f(z) : sigmoid_f(z);
            z_s[j] = a;
            __syncthreads();

            if (j < D_) {
                float ig = z_s[j];
                float fg = z_s[j + D_];
                float gg = z_s[j + 2 * D_];
                float og = z_s[j + 3 * D_];
                float c  = (l == 0) ? c0 : (l == 1) ? c1 : c2;
                float cn = fg * c + ig * gg;
                if (l == 0) c0 = cn; else if (l == 1) c1 = cn; else c2 = cn;
                float hn = og * tanh_f(cn);
                h_s[l][j] = hn;
                if (l == NL - 1) hb[t * D_ + j] = hn;
            }
            __syncthreads();
        }
        xr = xn;
    }
}

// ---------------------------------------------------------------------------
// Dense(65) epilogue: out[b,t,:] = h_top[b,t,:] @ Wd + bd
// ---------------------------------------------------------------------------
#define ROWS_PB 32
__global__ void dense_kernel(const float* __restrict__ Wd,
                             const float* __restrict__ bd,
                             float* __restrict__ out)
{
    __shared__ float Wds[D_ * D_];
    __shared__ float bds[D_];
    __shared__ float hrow[ROWS_PB][D_];

    const int tx  = threadIdx.x;          // 0..64
    const int ty  = threadIdx.y;          // 0..7
    const int tid = ty * D_ + tx;         // 0..519

    for (int i = tid; i < D_ * D_; i += D_ * 8) Wds[i] = Wd[i];
    if (tid < D_) bds[tid] = bd[tid];

    const size_t row0 = (size_t)blockIdx.x * ROWS_PB;
    for (int i = tid; i < ROWS_PB * D_; i += D_ * 8)
        hrow[i / D_][i % D_] = g_hs[row0 * D_ + i];
    __syncthreads();

    for (int r = ty; r < ROWS_PB; r += 8) {
        float acc = bds[tx];
#pragma unroll
        for (int k = 0; k < D_; k++)
            acc += hrow[r][k] * Wds[k * D_ + tx];
        out[(row0 + r) * D_ + tx] = acc;
    }
}

// ---------------------------------------------------------------------------
extern "C" void kernel_launch(void* const* d_in, const int* in_sizes, int n_in,
                              void* d_out, int out_size)
{
    const float* x  = (const float*)d_in[0];
    const float* W  = (const float*)d_in[1];
    const float* U  = (const float*)d_in[2];
    const float* b  = (const float*)d_in[3];
    const float* Wd = (const float*)d_in[4];
    const float* bd = (const float*)d_in[5];
    float* out = (float*)d_out;

    lstm_kernel<<<B_, G4>>>(x, W, U, b);

    dim3 db(D_, 8);
    dense_kernel<<<(B_ * T_) / ROWS_PB, db>>>(Wd, bd, out);
}